// round 4
// baseline (speedup 1.0000x reference)
#include <cuda_runtime.h>
#include <math.h>

// Problem constants
#define KK 64
#define DD 64
#define BB 16
#define NTOK 16384
#define TT 64                           // tokens per chunk
#define NCHUNK_TOTAL (BB * NTOK / TT)   // 4096 chunks
#define GRID 444                        // 148 SMs x occ 3
#define NTHREADS 256
#define PSIZE (KK + 2 * KK * DD)        // 8256 partial floats per slot

#define FSTRIDE 66                      // f_sh row stride (x only), conflict-free
#define LSTRIDE 66                      // logits/Q row stride
#define LOG2E 1.4426950408889634f
#define LN2PI 1.8378770664093453f

// smem layout (floats): W[8192] | f[64*66] | L[64*66] | c[64]
#define SM_W 0
#define SM_F 8192
#define SM_L (SM_F + 64 * FSTRIDE)      // 12416
#define SM_C (SM_L + 64 * LSTRIDE)      // 16640
#define SMEM_FLOATS (SM_C + 64)         // 16704
#define SMEM_BYTES (SMEM_FLOATS * 4)    // 66816  (x3 = 200448 <= 228KB)

__device__ float g_scratch[GRID * 2 * PSIZE];
__device__ int   g_tag[GRID * 2];

typedef unsigned long long ull;

// ---------------- packed f32x2 helpers (sm_100+) ----------------
__device__ __forceinline__ void fma2(ull &d, ull a, ull b) {
    asm("fma.rn.f32x2 %0, %1, %2, %0;" : "+l"(d) : "l"(a), "l"(b));
}
__device__ __forceinline__ void mul2(ull &d, ull a, ull b) {
    asm("mul.rn.f32x2 %0, %1, %2;" : "=l"(d) : "l"(a), "l"(b));
}
__device__ __forceinline__ ull pack2(float x) {
    ull r;
    asm("mov.b64 %0, {%1, %1};" : "=l"(r) : "f"(x));
    return r;
}
__device__ __forceinline__ float2 unpk(ull v) {
    float2 r;
    asm("mov.b64 {%0, %1}, %2;" : "=f"(r.x), "=f"(r.y) : "l"(v));
    return r;
}
__device__ __forceinline__ float ex2f(float x) {
    float r;
    asm("ex2.approx.f32 %0, %1;" : "=f"(r) : "f"(x));
    return r;
}

// ---------------- main kernel ------------------------------------
extern __shared__ float smem[];

__global__ __launch_bounds__(NTHREADS, 3)
void fv_main_kernel(const float* __restrict__ x,
                    const float* __restrict__ pi,
                    const float* __restrict__ mu,
                    const float* __restrict__ var) {
    float* W_sh = smem + SM_W;
    float* f_sh = smem + SM_F;
    float* L_sh = smem + SM_L;
    float* c_sh = smem + SM_C;

    const int tid = threadIdx.x;
    const int bid = blockIdx.x;

    // chunk range for this CTA
    const int s_lo = (bid * NCHUNK_TOTAL) / GRID;
    const int s_hi = ((bid + 1) * NCHUNK_TOTAL) / GRID;

    const float4* xg = (const float4*)x;

    // prefetch first chunk (latency overlapped with prep below)
    float4 pf[4];
#pragma unroll
    for (int it = 0; it < 4; it++)
        pf[it] = xg[(size_t)s_lo * 1024 + tid + NTHREADS * it];

    // ---- prep: fold weights/constants into smem (per-CTA) ----
    // W[k, d] = -0.5/var*log2e (j<64) ; W[k, 64+d] = mu/var*log2e
    for (int i = tid; i < KK * 128; i += NTHREADS) {
        int k = i >> 7, j = i & 127, d = j & 63;
        float v = var[k * DD + d];
        float iv = __frcp_rn(v);
        float w = (j < 64) ? (-0.5f * iv * LOG2E) : (mu[k * DD + d] * iv * LOG2E);
        W_sh[i] = w;
    }
    {   // c[k] = (-0.5*(D ln2pi + sum(log v + m^2/v)) + ln pi)*log2e
        int k = tid >> 2, seg = tid & 3;
        float part = 0.f;
#pragma unroll 4
        for (int d = seg * 16; d < seg * 16 + 16; d++) {
            float v = var[k * DD + d];
            float m = mu[k * DD + d];
            part += __logf(v) + m * m * __frcp_rn(v);
        }
        part += __shfl_xor_sync(0xffffffffu, part, 1);
        part += __shfl_xor_sync(0xffffffffu, part, 2);
        if (seg == 0)
            c_sh[k] = (-0.5f * (64.0f * LN2PI + part) + __logf(pi[k])) * LOG2E;
    }

    // phase-3 accumulators: thread (ki, di) owns k in {ki+16i}, d quad 4di..4di+3
    const int ki = tid >> 4;
    const int di = tid & 15;
    ull aqx[4][2], aqx2[4][2];
    float qsum[4];
#pragma unroll
    for (int i = 0; i < 4; i++) {
        aqx[i][0] = 0ull; aqx[i][1] = 0ull;
        aqx2[i][0] = 0ull; aqx2[i][1] = 0ull;
        qsum[i] = 0.f;
    }
    int slot = 0;
    int cur_b = s_lo >> 8;      // 256 chunks per batch

    // phase-1 mapping: tokens tg+16*t4, k = 4*kg+k4
    const int tg = tid & 15;
    const int kg = tid >> 4;

    for (int c = s_lo; c < s_hi; c++) {
        __syncthreads();   // f_sh/L_sh reuse barrier (covers prep on first iter)

        // ---- phase 0: stage x into f_sh from prefetch regs ----
#pragma unroll
        for (int it = 0; it < 4; it++) {
            int f4 = tid + NTHREADS * it;       // 0..1023 float4 slots
            int t  = f4 >> 4;
            int c4 = f4 & 15;
            float4 v = pf[it];
            float* p = f_sh + t * FSTRIDE + 4 * c4;
            *(float2*)p       = make_float2(v.x, v.y);
            *(float2*)(p + 2) = make_float2(v.z, v.w);
        }
        __syncthreads();

        // ---- phase 1: logits; 4 tokens x 4 k per thread; square on the fly ----
        {
            ull acc[4][4];
#pragma unroll
            for (int a = 0; a < 4; a++)
#pragma unroll
                for (int cc = 0; cc < 4; cc++) acc[a][cc] = 0ull;

            const float* wbase = W_sh + (kg * 4) * 128;
#pragma unroll 4
            for (int jp = 0; jp < 32; jp++) {
                ull fvp[4], sqp[4];
#pragma unroll
                for (int t4 = 0; t4 < 4; t4++) {
                    fvp[t4] = *(const ull*)(f_sh + (tg + 16 * t4) * FSTRIDE + 2 * jp);
                    mul2(sqp[t4], fvp[t4], fvp[t4]);
                }
#pragma unroll
                for (int k4 = 0; k4 < 4; k4++) {
                    ull w1 = *(const ull*)(wbase + k4 * 128 + 2 * jp);
                    ull w2 = *(const ull*)(wbase + k4 * 128 + 64 + 2 * jp);
#pragma unroll
                    for (int t4 = 0; t4 < 4; t4++) {
                        fma2(acc[t4][k4], sqp[t4], w1);
                        fma2(acc[t4][k4], fvp[t4], w2);
                    }
                }
            }
#pragma unroll
            for (int t4 = 0; t4 < 4; t4++) {
                int t = tg + 16 * t4;
#pragma unroll
                for (int k4 = 0; k4 < 4; k4++) {
                    int k = 4 * kg + k4;
                    float2 a = unpk(acc[t4][k4]);
                    L_sh[t * LSTRIDE + k] = a.x + a.y + c_sh[k];
                }
            }
        }
        __syncthreads();

        // ---- phase 2: softmax over K=64 per token (warp per 8 tokens) ----
        {
            const int wid = tid >> 5;
            const int lane = tid & 31;
#pragma unroll
            for (int t8 = 0; t8 < 8; t8++) {
                int t = wid * 8 + t8;
                float l0 = L_sh[t * LSTRIDE + lane];
                float l1 = L_sh[t * LSTRIDE + lane + 32];
                float m = fmaxf(l0, l1);
#pragma unroll
                for (int o = 16; o > 0; o >>= 1)
                    m = fmaxf(m, __shfl_xor_sync(0xffffffffu, m, o));
                float e0 = ex2f(l0 - m);
                float e1 = ex2f(l1 - m);
                float ssum = e0 + e1;
#pragma unroll
                for (int o = 16; o > 0; o >>= 1)
                    ssum += __shfl_xor_sync(0xffffffffu, ssum, o);
                float inv = __frcp_rn(ssum);
                L_sh[t * LSTRIDE + lane]      = e0 * inv;
                L_sh[t * LSTRIDE + lane + 32] = e1 * inv;
            }
        }
        __syncthreads();

        // prefetch next chunk here (lowest register-pressure point;
        // phase 3 below gives ~2000 cycles to cover the DRAM latency)
        if (c + 1 < s_hi) {
#pragma unroll
            for (int it = 0; it < 4; it++)
                pf[it] = xg[(size_t)(c + 1) * 1024 + tid + NTHREADS * it];
        }

        // ---- phase 3: accumulate Q_sum, Q^T x, Q^T x^2 ----
        {
#pragma unroll 2
            for (int t = 0; t < TT; t++) {
                const float* frow = f_sh + t * FSTRIDE;
                const float* lrow = L_sh + t * LSTRIDE;
                ull x0 = *(const ull*)(frow + 4 * di);
                ull x1 = *(const ull*)(frow + 4 * di + 2);
                ull s0, s1;
                mul2(s0, x0, x0);
                mul2(s1, x1, x1);
#pragma unroll
                for (int i = 0; i < 4; i++) {
                    float q = lrow[ki + 16 * i];
                    ull q2 = pack2(q);
                    fma2(aqx[i][0], q2, x0);
                    fma2(aqx[i][1], q2, x1);
                    fma2(aqx2[i][0], q2, s0);
                    fma2(aqx2[i][1], q2, s1);
                    if (di == 0) qsum[i] += q;
                }
            }
        }

        // ---- flush partials at batch boundary / end of range ----
        int nb = (c + 1) >> 8;
        if (c + 1 == s_hi || nb != cur_b) {
            float* outp = g_scratch + (size_t)(bid * 2 + slot) * PSIZE;
            if (tid == 0) g_tag[bid * 2 + slot] = cur_b;
            if (di == 0) {
#pragma unroll
                for (int i = 0; i < 4; i++) outp[ki + 16 * i] = qsum[i];
            }
#pragma unroll
            for (int i = 0; i < 4; i++) {
                int k = ki + 16 * i;
                float2 v0 = unpk(aqx[i][0]);
                float2 v1 = unpk(aqx[i][1]);
                float4 o; o.x = v0.x; o.y = v0.y; o.z = v1.x; o.w = v1.y;
                *(float4*)(outp + 64 + k * 64 + 4 * di) = o;
                float2 w0 = unpk(aqx2[i][0]);
                float2 w1 = unpk(aqx2[i][1]);
                float4 o2; o2.x = w0.x; o2.y = w0.y; o2.z = w1.x; o2.w = w1.y;
                *(float4*)(outp + 64 + 4096 + k * 64 + 4 * di) = o2;
            }
#pragma unroll
            for (int i = 0; i < 4; i++) {
                aqx[i][0] = 0ull; aqx[i][1] = 0ull;
                aqx2[i][0] = 0ull; aqx2[i][1] = 0ull;
                qsum[i] = 0.f;
            }
            slot++;
            cur_b = nb;
        }
    }
    if (tid == 0) {
        for (int sl = slot; sl < 2; sl++) g_tag[bid * 2 + sl] = -1;
    }
}

// ---------------- reduce + finalize ------------------------------
__global__ void fv_reduce_kernel(const float* __restrict__ pi,
                                 const float* __restrict__ mu,
                                 const float* __restrict__ var,
                                 float* __restrict__ out) {
    int idx = blockIdx.x * blockDim.x + threadIdx.x;   // 0 .. B*K*D-1
    if (idx >= BB * KK * DD) return;
    int b  = idx >> 12;
    int kd = idx & 4095;
    int k  = kd >> 6;
    int d  = kd & 63;

    // CTAs whose chunk range can overlap batch b (monotone partition)
    int i_lo = (GRID * b) / BB - 1;       if (i_lo < 0) i_lo = 0;
    int i_hi = (GRID * (b + 1)) / BB + 1; if (i_hi > GRID - 1) i_hi = GRID - 1;

    float qs = 0.f, qx = 0.f, qx2 = 0.f;
    for (int i = i_lo; i <= i_hi; i++) {
#pragma unroll
        for (int sl = 0; sl < 2; sl++) {
            int sid = 2 * i + sl;
            if (g_tag[sid] == b) {
                const float* p = g_scratch + (size_t)sid * PSIZE;
                qs  += p[k];
                qx  += p[64 + kd];
                qx2 += p[64 + 4096 + kd];
            }
        }
    }
    const float invN = 1.0f / (float)NTOK;
    qs *= invN; qx *= invN; qx2 *= invN;

    float m = mu[kd];
    float v = var[kd];
    float* ob = out + (size_t)b * 8256;
    ob[64 + kd]        = qx - qs * m;
    ob[64 + 4096 + kd] = -qx2 - qs * m * m + qs * v + 2.0f * qx * m;
    if (d == 0) ob[k] = qs - pi[k];
}

// ---------------- launch -----------------------------------------
extern "C" void kernel_launch(void* const* d_in, const int* in_sizes, int n_in,
                              void* d_out, int out_size) {
    const float* x   = (const float*)d_in[0];
    const float* pi  = (const float*)d_in[1];
    const float* mu  = (const float*)d_in[2];
    const float* var = (const float*)d_in[3];
    float* out = (float*)d_out;

    cudaFuncSetAttribute(fv_main_kernel,
                         cudaFuncAttributeMaxDynamicSharedMemorySize, SMEM_BYTES);

    fv_main_kernel<<<GRID, NTHREADS, SMEM_BYTES>>>(x, pi, mu, var);
    fv_reduce_kernel<<<(BB * KK * DD + 255) / 256, 256>>>(pi, mu, var, out);
}

// round 5
// speedup vs baseline: 2.1095x; 2.1095x over previous
#include <cuda_runtime.h>
#include <math.h>

// Problem constants
#define KK 64
#define DD 64
#define BB 16
#define NTOK 16384
#define TT 32                           // tokens per chunk
#define NCHUNK_TOTAL (BB * NTOK / TT)   // 8192 chunks
#define CH_PER_B (NTOK / TT)            // 512 chunks per batch
#define GRID 444                        // 148 SMs x occ 3
#define NTHREADS 256
#define PSIZE (KK + 2 * KK * DD)        // 8256 partial floats per slot

#define WSTRIDE 132                     // W_sh row stride (conflict-free)
#define FSTRIDE 132                     // f_sh row stride ([x^2|x], 128 used)
#define LSTRIDE 66                      // logits/Q row stride
#define LOG2E 1.4426950408889634f
#define LN2PI 1.8378770664093453f

// smem layout (floats): W[64*132] | f[32*132] | L[32*66] | c[64] | stage[2048]
#define SM_W 0
#define SM_F (64 * WSTRIDE)                  // 8448
#define SM_L (SM_F + TT * FSTRIDE)           // 12672
#define SM_C (SM_L + TT * LSTRIDE)           // 14784
#define SM_STAGE (SM_C + 64)                 // 14848
#define SMEM_FLOATS (SM_STAGE + TT * DD)     // 16896
#define SMEM_BYTES (SMEM_FLOATS * 4)         // 67584 (x3 = 202752 <= 227KB)

__device__ float g_scratch[GRID * 2 * PSIZE];
__device__ int   g_tag[GRID * 2];

typedef unsigned long long ull;

// ---------------- packed f32x2 helpers (sm_100+) ----------------
__device__ __forceinline__ void fma2(ull &d, ull a, ull b) {
    asm("fma.rn.f32x2 %0, %1, %2, %0;" : "+l"(d) : "l"(a), "l"(b));
}
__device__ __forceinline__ ull pack2(float x) {
    ull r;
    asm("mov.b64 %0, {%1, %1};" : "=l"(r) : "f"(x));
    return r;
}
__device__ __forceinline__ float2 unpk(ull v) {
    float2 r;
    asm("mov.b64 {%0, %1}, %2;" : "=f"(r.x), "=f"(r.y) : "l"(v));
    return r;
}
__device__ __forceinline__ float ex2f(float x) {
    float r;
    asm("ex2.approx.f32 %0, %1;" : "=f"(r) : "f"(x));
    return r;
}
__device__ __forceinline__ void cpasync16(float* dst_sh, const float* src) {
    unsigned saddr = (unsigned)__cvta_generic_to_shared(dst_sh);
    asm volatile("cp.async.cg.shared.global [%0], [%1], 16;" :: "r"(saddr), "l"(src));
}
__device__ __forceinline__ void cpcommit() { asm volatile("cp.async.commit_group;"); }
__device__ __forceinline__ void cpwait0()  { asm volatile("cp.async.wait_group 0;"); }

// ---------------- main kernel ------------------------------------
extern __shared__ float smem[];

__global__ __launch_bounds__(NTHREADS, 3)
void fv_main_kernel(const float* __restrict__ x,
                    const float* __restrict__ pi,
                    const float* __restrict__ mu,
                    const float* __restrict__ var) {
    float* W_sh  = smem + SM_W;
    float* f_sh  = smem + SM_F;
    float* L_sh  = smem + SM_L;
    float* c_sh  = smem + SM_C;
    float* stage = smem + SM_STAGE;

    const int tid = threadIdx.x;
    const int bid = blockIdx.x;

    // chunk range for this CTA
    const int s_lo = (bid * NCHUNK_TOTAL) / GRID;
    const int s_hi = ((bid + 1) * NCHUNK_TOTAL) / GRID;

    // ---- prologue: stage first chunk via cp.async (no registers held) ----
    {
        const float* src = x + (size_t)s_lo * (TT * DD);
        cpasync16(stage + tid * 4, src + tid * 4);
        cpasync16(stage + (tid + NTHREADS) * 4, src + (tid + NTHREADS) * 4);
        cpcommit();
    }

    // ---- prep: fold weights/constants into smem (per-CTA) ----
    // W_sh[k][0..63] = -0.5/var*log2e ; W_sh[k][64..127] = mu/var*log2e
    for (int i = tid; i < KK * 128; i += NTHREADS) {
        int k = i >> 7, j = i & 127, d = j & 63;
        float v = var[k * DD + d];
        float iv = __frcp_rn(v);
        float w = (j < 64) ? (-0.5f * iv * LOG2E) : (mu[k * DD + d] * iv * LOG2E);
        W_sh[k * WSTRIDE + j] = w;
    }
    {   // c[k] = (-0.5*(D ln2pi + sum(log v + m^2/v)) + ln pi)*log2e
        int k = tid >> 2, seg = tid & 3;
        float part = 0.f;
#pragma unroll 4
        for (int d = seg * 16; d < seg * 16 + 16; d++) {
            float v = var[k * DD + d];
            float m = mu[k * DD + d];
            part += __logf(v) + m * m * __frcp_rn(v);
        }
        part += __shfl_xor_sync(0xffffffffu, part, 1);
        part += __shfl_xor_sync(0xffffffffu, part, 2);
        if (seg == 0)
            c_sh[k] = (-0.5f * (64.0f * LN2PI + part) + __logf(pi[k])) * LOG2E;
    }

    // phase-3 accumulators: thread (ki, di) owns k in {ki+16i}, d quad 4di..4di+3
    const int ki = tid >> 4;
    const int di = tid & 15;
    ull aqx[4][2], aqx2[4][2];
    float qsum[4];
#pragma unroll
    for (int i = 0; i < 4; i++) {
        aqx[i][0] = 0ull; aqx[i][1] = 0ull;
        aqx2[i][0] = 0ull; aqx2[i][1] = 0ull;
        qsum[i] = 0.f;
    }
    int slot = 0;
    int cur_b = s_lo / CH_PER_B;

    // phase-1 mapping: tokens tg+8*t4 (t4=0..3), k in {kg, kg+32}
    const int tg = tid & 7;
    const int kg = tid >> 3;

    for (int c = s_lo; c < s_hi; c++) {
        cpwait0();
        __syncthreads();   // stage ready everywhere; f/L free (covers prep on 1st iter)

        // ---- phase 0: f = [x^2 | x] from stage into f_sh ----
#pragma unroll
        for (int it = 0; it < 2; it++) {
            int f4 = tid + NTHREADS * it;       // 0..511 float4 slots
            int t  = f4 >> 4;
            int c4 = f4 & 15;
            float4 v = *(const float4*)(stage + 4 * f4);
            float* frow = f_sh + t * FSTRIDE;
            *(float4*)(frow + 64 + 4 * c4) = v;
            float4 s;
            s.x = v.x * v.x; s.y = v.y * v.y; s.z = v.z * v.z; s.w = v.w * v.w;
            *(float4*)(frow + 4 * c4) = s;
        }
        __syncthreads();

        // stage next chunk (lands during phases 1-3; zero register cost)
        if (c + 1 < s_hi) {
            const float* src = x + (size_t)(c + 1) * (TT * DD);
            cpasync16(stage + tid * 4, src + tid * 4);
            cpasync16(stage + (tid + NTHREADS) * 4, src + (tid + NTHREADS) * 4);
            cpcommit();
        }

        // ---- phase 1: logits; 4 tokens x 2 k per thread ----
        {
            ull acc0[4], acc1[4];
#pragma unroll
            for (int a = 0; a < 4; a++) { acc0[a] = 0ull; acc1[a] = 0ull; }

            const float* wr0 = W_sh + kg * WSTRIDE;
            const float* wr1 = W_sh + (kg + 32) * WSTRIDE;
#pragma unroll 4
            for (int jp = 0; jp < 64; jp++) {
                ull w0 = *(const ull*)(wr0 + 2 * jp);
                ull w1 = *(const ull*)(wr1 + 2 * jp);
#pragma unroll
                for (int t4 = 0; t4 < 4; t4++) {
                    ull fv = *(const ull*)(f_sh + (tg + 8 * t4) * FSTRIDE + 2 * jp);
                    fma2(acc0[t4], fv, w0);
                    fma2(acc1[t4], fv, w1);
                }
            }
#pragma unroll
            for (int t4 = 0; t4 < 4; t4++) {
                int t = tg + 8 * t4;
                float2 a0 = unpk(acc0[t4]);
                float2 a1 = unpk(acc1[t4]);
                L_sh[t * LSTRIDE + kg]      = a0.x + a0.y + c_sh[kg];
                L_sh[t * LSTRIDE + kg + 32] = a1.x + a1.y + c_sh[kg + 32];
            }
        }
        __syncthreads();

        // ---- phase 2: softmax over K=64 per token (warp per 4 tokens) ----
        {
            const int wid = tid >> 5;
            const int lane = tid & 31;
#pragma unroll
            for (int t8 = 0; t8 < 4; t8++) {
                int t = wid * 4 + t8;
                float l0 = L_sh[t * LSTRIDE + lane];
                float l1 = L_sh[t * LSTRIDE + lane + 32];
                float m = fmaxf(l0, l1);
#pragma unroll
                for (int o = 16; o > 0; o >>= 1)
                    m = fmaxf(m, __shfl_xor_sync(0xffffffffu, m, o));
                float e0 = ex2f(l0 - m);
                float e1 = ex2f(l1 - m);
                float ssum = e0 + e1;
#pragma unroll
                for (int o = 16; o > 0; o >>= 1)
                    ssum += __shfl_xor_sync(0xffffffffu, ssum, o);
                float inv = __frcp_rn(ssum);
                L_sh[t * LSTRIDE + lane]      = e0 * inv;
                L_sh[t * LSTRIDE + lane + 32] = e1 * inv;
            }
        }
        __syncthreads();

        // ---- phase 3: accumulate Q_sum, Q^T x, Q^T x^2 ----
        {
#pragma unroll 2
            for (int t = 0; t < TT; t++) {
                const float* frow = f_sh + t * FSTRIDE;
                const float* lrow = L_sh + t * LSTRIDE;
                ulonglong2 sq = *(const ulonglong2*)(frow + 4 * di);       // x^2 quad
                ulonglong2 xq = *(const ulonglong2*)(frow + 64 + 4 * di);  // x quad
#pragma unroll
                for (int i = 0; i < 4; i++) {
                    float q = lrow[ki + 16 * i];
                    ull q2 = pack2(q);
                    fma2(aqx[i][0], q2, xq.x);
                    fma2(aqx[i][1], q2, xq.y);
                    fma2(aqx2[i][0], q2, sq.x);
                    fma2(aqx2[i][1], q2, sq.y);
                    if (di == 0) qsum[i] += q;
                }
            }
        }

        // ---- flush partials at batch boundary / end of range ----
        int nb = (c + 1) / CH_PER_B;
        if (c + 1 == s_hi || nb != cur_b) {
            float* outp = g_scratch + (size_t)(bid * 2 + slot) * PSIZE;
            if (tid == 0) g_tag[bid * 2 + slot] = cur_b;
            if (di == 0) {
#pragma unroll
                for (int i = 0; i < 4; i++) outp[ki + 16 * i] = qsum[i];
            }
#pragma unroll
            for (int i = 0; i < 4; i++) {
                int k = ki + 16 * i;
                float2 v0 = unpk(aqx[i][0]);
                float2 v1 = unpk(aqx[i][1]);
                float4 o; o.x = v0.x; o.y = v0.y; o.z = v1.x; o.w = v1.y;
                *(float4*)(outp + 64 + k * 64 + 4 * di) = o;
                float2 w0 = unpk(aqx2[i][0]);
                float2 w1 = unpk(aqx2[i][1]);
                float4 o2; o2.x = w0.x; o2.y = w0.y; o2.z = w1.x; o2.w = w1.y;
                *(float4*)(outp + 64 + 4096 + k * 64 + 4 * di) = o2;
            }
#pragma unroll
            for (int i = 0; i < 4; i++) {
                aqx[i][0] = 0ull; aqx[i][1] = 0ull;
                aqx2[i][0] = 0ull; aqx2[i][1] = 0ull;
                qsum[i] = 0.f;
            }
            slot++;
            cur_b = nb;
        }
    }
    if (tid == 0) {
        for (int sl = slot; sl < 2; sl++) g_tag[bid * 2 + sl] = -1;
    }
}

// ---------------- reduce + finalize ------------------------------
__global__ void fv_reduce_kernel(const float* __restrict__ pi,
                                 const float* __restrict__ mu,
                                 const float* __restrict__ var,
                                 float* __restrict__ out) {
    int idx = blockIdx.x * blockDim.x + threadIdx.x;   // 0 .. B*K*D-1
    if (idx >= BB * KK * DD) return;
    int b  = idx >> 12;
    int kd = idx & 4095;
    int k  = kd >> 6;
    int d  = kd & 63;

    // CTAs whose chunk range can overlap batch b (monotone partition)
    int i_lo = (GRID * b) / BB - 1;       if (i_lo < 0) i_lo = 0;
    int i_hi = (GRID * (b + 1)) / BB + 1; if (i_hi > GRID - 1) i_hi = GRID - 1;

    float qs = 0.f, qx = 0.f, qx2 = 0.f;
    for (int i = i_lo; i <= i_hi; i++) {
#pragma unroll
        for (int sl = 0; sl < 2; sl++) {
            int sid = 2 * i + sl;
            if (g_tag[sid] == b) {
                const float* p = g_scratch + (size_t)sid * PSIZE;
                qs  += p[k];
                qx  += p[64 + kd];
                qx2 += p[64 + 4096 + kd];
            }
        }
    }
    const float invN = 1.0f / (float)NTOK;
    qs *= invN; qx *= invN; qx2 *= invN;

    float m = mu[kd];
    float v = var[kd];
    float* ob = out + (size_t)b * 8256;
    ob[64 + kd]        = qx - qs * m;
    ob[64 + 4096 + kd] = -qx2 - qs * m * m + qs * v + 2.0f * qx * m;
    if (d == 0) ob[k] = qs - pi[k];
}

// ---------------- launch -----------------------------------------
extern "C" void kernel_launch(void* const* d_in, const int* in_sizes, int n_in,
                              void* d_out, int out_size) {
    const float* x   = (const float*)d_in[0];
    const float* pi  = (const float*)d_in[1];
    const float* mu  = (const float*)d_in[2];
    const float* var = (const float*)d_in[3];
    float* out = (float*)d_out;

    cudaFuncSetAttribute(fv_main_kernel,
                         cudaFuncAttributeMaxDynamicSharedMemorySize, SMEM_BYTES);

    fv_main_kernel<<<GRID, NTHREADS, SMEM_BYTES>>>(x, pi, mu, var);
    fv_reduce_kernel<<<(BB * KK * DD + 255) / 256, 256>>>(pi, mu, var, out);
}

// round 6
// speedup vs baseline: 2.4374x; 1.1554x over previous
#include <cuda_runtime.h>
#include <math.h>

// Problem constants
#define KK 64
#define DD 64
#define BB 16
#define NTOK 16384
#define TT 64                           // tokens per chunk
#define NCHUNK_TOTAL (BB * NTOK / TT)   // 4096 chunks
#define CH_PER_B (NTOK / TT)            // 256 chunks per batch
#define GRID 296                        // 148 SMs x occ 2, single wave
#define NTHREADS 256
#define PSIZE (KK + 2 * KK * DD)        // 8256 partial floats per slot

#define WSTRIDE 132                     // W_sh row stride (conflict-free)
#define FSTRIDE 132                     // f_sh row stride [x^2|x]
#define QSTRIDE 132                     // Ldup row stride (dup pairs, 128 used)
#define LOG2E 1.4426950408889634f
#define LN2PI 1.8378770664093453f

// smem layout (floats): W[64*132] | f[64*132] | Ldup[64*132] | c[64] | qsw[8*66]
#define SM_W 0
#define SM_F (64 * WSTRIDE)                  // 8448
#define SM_Q (SM_F + 64 * FSTRIDE)           // 16896
#define SM_C (SM_Q + 64 * QSTRIDE)           // 25344
#define SM_QS (SM_C + 64)                    // 25408
#define SMEM_FLOATS (SM_QS + 8 * 66)         // 25936
#define SMEM_BYTES (SMEM_FLOATS * 4)         // 103744 (x2 <= 227KB)

__device__ float g_scratch[GRID * 2 * PSIZE];
__device__ int   g_tag[GRID * 2];

typedef unsigned long long ull;

// ---------------- packed f32x2 helpers (sm_100+) ----------------
__device__ __forceinline__ void fma2(ull &d, ull a, ull b) {
    asm("fma.rn.f32x2 %0, %1, %2, %0;" : "+l"(d) : "l"(a), "l"(b));
}
__device__ __forceinline__ float2 unpk(ull v) {
    float2 r;
    asm("mov.b64 {%0, %1}, %2;" : "=f"(r.x), "=f"(r.y) : "l"(v));
    return r;
}
__device__ __forceinline__ float ex2f(float x) {
    float r;
    asm("ex2.approx.f32 %0, %1;" : "=f"(r) : "f"(x));
    return r;
}
// store a duplicated pair {v, v} with one STS.64, no pack needed
__device__ __forceinline__ void sts64dup(float* dst_sh, float v) {
    unsigned saddr = (unsigned)__cvta_generic_to_shared(dst_sh);
    asm volatile("st.shared.v2.f32 [%0], {%1, %1};" :: "r"(saddr), "f"(v));
}

// ---------------- main kernel (persistent, occ 2) -----------------
extern __shared__ float smem[];

__global__ __launch_bounds__(NTHREADS, 2)
void fv_main_kernel(const float* __restrict__ x,
                    const float* __restrict__ pi,
                    const float* __restrict__ mu,
                    const float* __restrict__ var) {
    float* W_sh  = smem + SM_W;
    float* f_sh  = smem + SM_F;
    float* Q_sh  = smem + SM_Q;    // logits then responsibilities, dup pairs
    float* c_sh  = smem + SM_C;
    float* qs_sh = smem + SM_QS;   // per-warp Q_sum partials [8][66]

    const int tid = threadIdx.x;
    const int bid = blockIdx.x;

    // chunk range for this CTA
    const int s_lo = (bid * NCHUNK_TOTAL) / GRID;
    const int s_hi = ((bid + 1) * NCHUNK_TOTAL) / GRID;

    const float4* xg = (const float4*)x;

    // prefetch first chunk (latency overlapped with prep)
    float4 pf[4];
#pragma unroll
    for (int it = 0; it < 4; it++)
        pf[it] = xg[(size_t)s_lo * 1024 + tid + NTHREADS * it];

    // ---- prep: fold weights/constants into smem (per-CTA) ----
    for (int i = tid; i < KK * 128; i += NTHREADS) {
        int k = i >> 7, j = i & 127, d = j & 63;
        float v = var[k * DD + d];
        float iv = __frcp_rn(v);
        float w = (j < 64) ? (-0.5f * iv * LOG2E) : (mu[k * DD + d] * iv * LOG2E);
        W_sh[k * WSTRIDE + j] = w;
    }
    {   // c[k] = (-0.5*(D ln2pi + sum(log v + m^2/v)) + ln pi)*log2e
        int k = tid >> 2, seg = tid & 3;
        float part = 0.f;
#pragma unroll 4
        for (int d = seg * 16; d < seg * 16 + 16; d++) {
            float v = var[k * DD + d];
            float m = mu[k * DD + d];
            part += __logf(v) + m * m * __frcp_rn(v);
        }
        part += __shfl_xor_sync(0xffffffffu, part, 1);
        part += __shfl_xor_sync(0xffffffffu, part, 2);
        if (seg == 0)
            c_sh[k] = (-0.5f * (64.0f * LN2PI + part) + __logf(pi[k])) * LOG2E;
    }

    // phase-3 accumulators: thread (ki, di) owns k in {ki+16i}, d quad 4di..4di+3
    const int ki = tid >> 4;
    const int di = tid & 15;
    ull aqx[4][2], aqx2[4][2];
#pragma unroll
    for (int i = 0; i < 4; i++) {
        aqx[i][0] = 0ull; aqx[i][1] = 0ull;
        aqx2[i][0] = 0ull; aqx2[i][1] = 0ull;
    }
    // per-warp Q_sum partials (k = lane, lane+32), accumulated in softmax
    float qs0 = 0.f, qs1 = 0.f;

    int slot = 0;
    int cur_b = s_lo / CH_PER_B;

    // phase-1 mapping: tokens tg+16*t4, k = 4*kg+k4
    const int tg = tid & 15;
    const int kg = tid >> 4;
    const int wid = tid >> 5;
    const int lane = tid & 31;

    for (int c = s_lo; c < s_hi; c++) {
        __syncthreads();   // f/Q reuse barrier (covers prep on first iter)

        // ---- phase 0: stage f = [x^2 | x] from prefetch regs ----
#pragma unroll
        for (int it = 0; it < 4; it++) {
            int f4 = tid + NTHREADS * it;       // 0..1023
            int t  = f4 >> 4;
            int c4 = f4 & 15;
            float4 v = pf[it];
            float* frow = f_sh + t * FSTRIDE;
            *(float4*)(frow + 64 + 4 * c4) = v;
            float4 s;
            s.x = v.x * v.x; s.y = v.y * v.y; s.z = v.z * v.z; s.w = v.w * v.w;
            *(float4*)(frow + 4 * c4) = s;
        }
        __syncthreads();

        // ---- phase 1: logits; 4 tokens x 4 k; wv held, fv streamed ----
        {
            ull acc[4][4];
#pragma unroll
            for (int a = 0; a < 4; a++)
#pragma unroll
                for (int cc = 0; cc < 4; cc++) acc[a][cc] = 0ull;

            const float* wbase = W_sh + (kg * 4) * WSTRIDE;
#pragma unroll 2
            for (int jp2 = 0; jp2 < 32; jp2++) {
                ulonglong2 wv[4];
#pragma unroll
                for (int k4 = 0; k4 < 4; k4++)
                    wv[k4] = *(const ulonglong2*)(wbase + k4 * WSTRIDE + 4 * jp2);
#pragma unroll
                for (int t4 = 0; t4 < 4; t4++) {
                    ulonglong2 fv = *(const ulonglong2*)(f_sh + (tg + 16 * t4) * FSTRIDE + 4 * jp2);
#pragma unroll
                    for (int k4 = 0; k4 < 4; k4++) {
                        fma2(acc[t4][k4], fv.x, wv[k4].x);
                        fma2(acc[t4][k4], fv.y, wv[k4].y);
                    }
                }
            }
            // epilogue: write duplicated (l,l) pairs
#pragma unroll
            for (int t4 = 0; t4 < 4; t4++) {
                int t = tg + 16 * t4;
#pragma unroll
                for (int k4 = 0; k4 < 4; k4++) {
                    int k = 4 * kg + k4;
                    float2 a = unpk(acc[t4][k4]);
                    sts64dup(Q_sh + t * QSTRIDE + 2 * k, a.x + a.y + c_sh[k]);
                }
            }
        }
        __syncthreads();

        // prefetch next chunk (covered by softmax + phase 3; low reg pressure here)
        if (c + 1 < s_hi) {
#pragma unroll
            for (int it = 0; it < 4; it++)
                pf[it] = xg[(size_t)(c + 1) * 1024 + tid + NTHREADS * it];
        }

        // ---- phase 2: softmax over K=64 per token; also build Q_sum ----
        {
#pragma unroll
            for (int t8 = 0; t8 < 8; t8++) {
                int t = wid * 8 + t8;
                float l0 = Q_sh[t * QSTRIDE + 2 * lane];
                float l1 = Q_sh[t * QSTRIDE + 2 * lane + 64];
                float m = fmaxf(l0, l1);
#pragma unroll
                for (int o = 16; o > 0; o >>= 1)
                    m = fmaxf(m, __shfl_xor_sync(0xffffffffu, m, o));
                float e0 = ex2f(l0 - m);
                float e1 = ex2f(l1 - m);
                float ssum = e0 + e1;
#pragma unroll
                for (int o = 16; o > 0; o >>= 1)
                    ssum += __shfl_xor_sync(0xffffffffu, ssum, o);
                float inv = __frcp_rn(ssum);
                float q0 = e0 * inv;
                float q1 = e1 * inv;
                sts64dup(Q_sh + t * QSTRIDE + 2 * lane, q0);
                sts64dup(Q_sh + t * QSTRIDE + 2 * lane + 64, q1);
                qs0 += q0;
                qs1 += q1;
            }
        }
        __syncthreads();

        // ---- phase 3: accumulate Q^T x, Q^T x^2 (dup-pair q via LDS.64) ----
        {
#pragma unroll 2
            for (int t = 0; t < TT; t++) {
                const float* frow = f_sh + t * FSTRIDE;
                const float* qrow = Q_sh + t * QSTRIDE;
                ulonglong2 sq = *(const ulonglong2*)(frow + 4 * di);       // x^2 quad
                ulonglong2 xq = *(const ulonglong2*)(frow + 64 + 4 * di);  // x quad
#pragma unroll
                for (int i = 0; i < 4; i++) {
                    ull q2 = *(const ull*)(qrow + 2 * (ki + 16 * i));      // (q,q)
                    fma2(aqx[i][0], q2, xq.x);
                    fma2(aqx[i][1], q2, xq.y);
                    fma2(aqx2[i][0], q2, sq.x);
                    fma2(aqx2[i][1], q2, sq.y);
                }
            }
        }

        // ---- flush partials at batch boundary / end of range ----
        int nb = (c + 1) / CH_PER_B;
        if (c + 1 == s_hi || nb != cur_b) {
            __syncthreads();
            qs_sh[wid * 66 + lane]      = qs0;
            qs_sh[wid * 66 + lane + 32] = qs1;
            __syncthreads();

            float* outp = g_scratch + (size_t)(bid * 2 + slot) * PSIZE;
            if (tid == 0) g_tag[bid * 2 + slot] = cur_b;
            if (di == 0) {
#pragma unroll
                for (int i = 0; i < 4; i++) {
                    int k = ki + 16 * i;
                    float qsk = 0.f;
#pragma unroll
                    for (int w = 0; w < 8; w++) qsk += qs_sh[w * 66 + k];
                    outp[k] = qsk;
                }
            }
#pragma unroll
            for (int i = 0; i < 4; i++) {
                int k = ki + 16 * i;
                float2 v0 = unpk(aqx[i][0]);
                float2 v1 = unpk(aqx[i][1]);
                float4 o; o.x = v0.x; o.y = v0.y; o.z = v1.x; o.w = v1.y;
                *(float4*)(outp + 64 + k * 64 + 4 * di) = o;
                float2 w0 = unpk(aqx2[i][0]);
                float2 w1 = unpk(aqx2[i][1]);
                float4 o2; o2.x = w0.x; o2.y = w0.y; o2.z = w1.x; o2.w = w1.y;
                *(float4*)(outp + 64 + 4096 + k * 64 + 4 * di) = o2;
            }
#pragma unroll
            for (int i = 0; i < 4; i++) {
                aqx[i][0] = 0ull; aqx[i][1] = 0ull;
                aqx2[i][0] = 0ull; aqx2[i][1] = 0ull;
            }
            qs0 = 0.f; qs1 = 0.f;
            slot++;
            cur_b = nb;
        }
    }
    if (tid == 0) {
        for (int sl = slot; sl < 2; sl++) g_tag[bid * 2 + sl] = -1;
    }
}

// ---------------- reduce + finalize ------------------------------
__global__ void fv_reduce_kernel(const float* __restrict__ pi,
                                 const float* __restrict__ mu,
                                 const float* __restrict__ var,
                                 float* __restrict__ out) {
    int idx = blockIdx.x * blockDim.x + threadIdx.x;   // 0 .. B*K*D-1
    if (idx >= BB * KK * DD) return;
    int b  = idx >> 12;
    int kd = idx & 4095;
    int k  = kd >> 6;
    int d  = kd & 63;

    // CTAs whose chunk range can overlap batch b (monotone partition)
    int i_lo = (GRID * b) / BB - 1;       if (i_lo < 0) i_lo = 0;
    int i_hi = (GRID * (b + 1)) / BB + 1; if (i_hi > GRID - 1) i_hi = GRID - 1;

    float qs = 0.f, qx = 0.f, qx2 = 0.f;
    float qsB = 0.f, qxB = 0.f, qx2B = 0.f;   // second accumulator for MLP
    int n = 2 * (i_hi - i_lo + 1);
    int base_sid = 2 * i_lo;
#pragma unroll 2
    for (int j = 0; j < n; j += 2) {
        int sid0 = base_sid + j;
        int sid1 = base_sid + j + 1;
        if (g_tag[sid0] == b) {
            const float* p = g_scratch + (size_t)sid0 * PSIZE;
            qs  += p[k];
            qx  += p[64 + kd];
            qx2 += p[64 + 4096 + kd];
        }
        if (g_tag[sid1] == b) {
            const float* p = g_scratch + (size_t)sid1 * PSIZE;
            qsB  += p[k];
            qxB  += p[64 + kd];
            qx2B += p[64 + 4096 + kd];
        }
    }
    qs += qsB; qx += qxB; qx2 += qx2B;

    const float invN = 1.0f / (float)NTOK;
    qs *= invN; qx *= invN; qx2 *= invN;

    float m = mu[kd];
    float v = var[kd];
    float* ob = out + (size_t)b * 8256;
    ob[64 + kd]        = qx - qs * m;
    ob[64 + 4096 + kd] = -qx2 - qs * m * m + qs * v + 2.0f * qx * m;
    if (d == 0) ob[k] = qs - pi[k];
}

// ---------------- launch -----------------------------------------
extern "C" void kernel_launch(void* const* d_in, const int* in_sizes, int n_in,
                              void* d_out, int out_size) {
    const float* x   = (const float*)d_in[0];
    const float* pi  = (const float*)d_in[1];
    const float* mu  = (const float*)d_in[2];
    const float* var = (const float*)d_in[3];
    float* out = (float*)d_out;

    cudaFuncSetAttribute(fv_main_kernel,
                         cudaFuncAttributeMaxDynamicSharedMemorySize, SMEM_BYTES);

    fv_main_kernel<<<GRID, NTHREADS, SMEM_BYTES>>>(x, pi, mu, var);
    fv_reduce_kernel<<<(BB * KK * DD + 255) / 256, 256>>>(pi, mu, var, out);
}